// round 8
// baseline (speedup 1.0000x reference)
#include <cuda_runtime.h>
#include <math.h>
#include <stdint.h>

// ---------------- problem constants ----------------
#define TOT_N   128000      // B*N nodes
#define NEDGE   512000      // total edges
#define NB      128         // batch of graphs
#define HID     64          // H
#define NHEADS  4
#define DH      16
#define FIN     32
#define NLAYERS 4
#define AOUT    15
#define OBSD    1500
#define HSZ     512
#define VH      128
#define FEATD   (AOUT + OBSD)   // 1515
#define FPAD    1536            // padded K for head GEMMs
#define KC      32              // GEMM K-chunk

// ---- fragment buffer offsets (in float4 units) ----
#define FR_WIN  0                 // (32/8)*(64/8)*32          = 1024
#define FR_WQ   1024              // 4 layers * 8*8*32 = 2048/l = 8192
#define FR_WK   9216
#define FR_WV   17408
#define FR_WO   25600
#define FR_W1   33792             // 4 * 8*16*32 = 4096/l      = 16384
#define FR_W2   50176             // 4 * 16*8*32 = 4096/l      = 16384
#define FR_WP1  66560             // 192*64*32                 = 393216
#define FR_WP2  459776            // 64*64*32                  = 131072
#define FR_WV1  590848            // 192*16*32                 = 98304
#define FR_WV2  689152            // 16*16*32                  = 8192
#define FR_TOT  697344

// ---------------- scratch (no allocs allowed) ----------------
__device__ float  g_x   [TOT_N * HID];
__device__ float  g_qkv [TOT_N * 3 * HID];
__device__ float  g_agg [TOT_N * HID];
__device__ float  g_h   [TOT_N * 2 * HID];
__device__ float4 g_frag[FR_TOT];
__device__ int    g_cnt[TOT_N];
__device__ int    g_off[TOT_N + 1];
__device__ int    g_csr[NEDGE];
__device__ float  g_feat[NB * FPAD];
__device__ float  g_obsP[NB * FPAD];
__device__ float  g_f1 [NB * HSZ];
__device__ float  g_f2 [NB * HSZ];
__device__ float  g_vh [NB * VH];
__device__ float  g_vh2[NB * VH];

// ---------------- tf32 helpers ----------------
__device__ __forceinline__ uint32_t f2tf(float x) {
    uint32_t r;
    asm("cvt.rna.tf32.f32 %0, %1;" : "=r"(r) : "f"(x));
    return r;
}

#define MMA_TF32(c, a, b0v, b1v) \
    asm volatile("mma.sync.aligned.m16n8k8.row.col.f32.tf32.tf32.f32 " \
        "{%0,%1,%2,%3}, {%4,%5,%6,%7}, {%8,%9}, {%0,%1,%2,%3};" \
        : "+f"((c)[0]), "+f"((c)[1]), "+f"((c)[2]), "+f"((c)[3]) \
        : "r"((a)[0]), "r"((a)[1]), "r"((a)[2]), "r"((a)[3]), "r"(b0v), "r"(b1v))

// ---------------- weight -> mma-fragment repack (hi/lo tf32, once per launch) ---------
// layout: dst[((k8*(N/8) + ntg)*32 + lane)] = (bh0, bh1, bl0, bl1) for that lane.
// lane = 4*gr + gc; bh0 = W[k8*8+gc][ntg*8+gr]; bh1 = W[k8*8+gc+4][ntg*8+gr].
// rows >= Ksrc read as 0 (K padding). layers stacked (src stride Ksrc*N, dst stride f4PerLayer).
__global__ void repack_kernel(const float* __restrict__ src, float4* __restrict__ dst,
                              int Ksrc, int Kpad, int N, int layers) {
    int f4PerLayer = (Kpad >> 3) * (N >> 3) * 32;
    int total = layers * f4PerLayer;
    int tid = blockIdx.x * 256 + threadIdx.x;
    if (tid >= total) return;
    int l = tid / f4PerLayer;
    int r = tid - l * f4PerLayer;
    int lane = r & 31;
    int rest = r >> 5;
    int nTG = N >> 3;
    int ntg = rest % nTG;
    int k8  = rest / nTG;
    int gr = lane >> 2, gc = lane & 3;
    int n  = ntg * 8 + gr;
    int k0 = k8 * 8 + gc, k1 = k0 + 4;
    const float* s = src + (size_t)l * Ksrc * N;
    float x0 = (k0 < Ksrc) ? s[(size_t)k0 * N + n] : 0.f;
    float x1 = (k1 < Ksrc) ? s[(size_t)k1 * N + n] : 0.f;
    float h0 = __uint_as_float(f2tf(x0));
    float h1 = __uint_as_float(f2tf(x1));
    float l0 = __uint_as_float(f2tf(x0 - h0));
    float l1 = __uint_as_float(f2tf(x1 - h1));
    dst[tid] = make_float4(h0, h1, l0, l1);
}

// ---------------- CSR build ----------------
__global__ void count_kernel(const int* __restrict__ dst) {
    int e = blockIdx.x * blockDim.x + threadIdx.x;
    if (e < NEDGE) atomicAdd(&g_cnt[dst[e]], 1);
}

__global__ void scan_kernel() {
    __shared__ int ssum[1024];
    int t = threadIdx.x;
    const int chunk = (TOT_N + 1023) / 1024;
    int start = t * chunk;
    int end = start + chunk; if (end > TOT_N) end = TOT_N;
    if (start > TOT_N) start = TOT_N;
    int s = 0;
    for (int i = start; i < end; i++) s += g_cnt[i];
    ssum[t] = s;
    __syncthreads();
    for (int d = 1; d < 1024; d <<= 1) {
        int v = 0;
        if (t >= d) v = ssum[t - d];
        __syncthreads();
        if (t >= d) ssum[t] += v;
        __syncthreads();
    }
    int run = (t > 0) ? ssum[t - 1] : 0;
    for (int i = start; i < end; i++) {
        int c = g_cnt[i];
        g_off[i] = run;
        run += c;
    }
    if (end == TOT_N) g_off[TOT_N] = run;
}

__global__ void scatter_kernel(const int* __restrict__ src, const int* __restrict__ dst) {
    int e = blockIdx.x * blockDim.x + threadIdx.x;
    if (e < NEDGE) {
        int d = dst[e];
        int pos = g_off[d] + atomicAdd(&g_cnt[d], 1);
        g_csr[pos] = src[e];
    }
}

// ---------------- per-(node,head) online-softmax attention (qkv packed [n,192]) --------
__global__ void attn_kernel(const float* __restrict__ qkv, float* __restrict__ agg) {
    int idx = blockIdx.x * blockDim.x + threadIdx.x;
    if (idx >= TOT_N * NHEADS) return;
    int n = idx >> 2;
    int h = idx & 3;
    const float4* qp = (const float4*)(qkv + (size_t)n * 192 + h * DH);
    float4 q0 = qp[0], q1 = qp[1], q2 = qp[2], q3 = qp[3];
    int e0 = g_off[n], e1 = g_off[n + 1];
    float M = -3.402823e38f, D = 0.f;
    float a[16];
#pragma unroll
    for (int i = 0; i < 16; i++) a[i] = 0.f;
    for (int e = e0; e < e1; e++) {
        int s = g_csr[e];
        const float4* kp = (const float4*)(qkv + (size_t)s * 192 + 64 + h * DH);
        float4 k0 = kp[0], k1 = kp[1], k2 = kp[2], k3 = kp[3];
        float dot = q0.x*k0.x + q0.y*k0.y + q0.z*k0.z + q0.w*k0.w
                  + q1.x*k1.x + q1.y*k1.y + q1.z*k1.z + q1.w*k1.w
                  + q2.x*k2.x + q2.y*k2.y + q2.z*k2.z + q2.w*k2.w
                  + q3.x*k3.x + q3.y*k3.y + q3.z*k3.z + q3.w*k3.w;
        dot *= 0.25f;
        float Mn = fmaxf(M, dot);
        float sc = __expf(M - Mn);
        float w  = __expf(dot - Mn);
        D = D * sc + w;
        const float4* vp = (const float4*)(qkv + (size_t)s * 192 + 128 + h * DH);
        float4 v0 = vp[0], v1 = vp[1], v2 = vp[2], v3 = vp[3];
        a[0]  = a[0]*sc  + w*v0.x;  a[1]  = a[1]*sc  + w*v0.y;
        a[2]  = a[2]*sc  + w*v0.z;  a[3]  = a[3]*sc  + w*v0.w;
        a[4]  = a[4]*sc  + w*v1.x;  a[5]  = a[5]*sc  + w*v1.y;
        a[6]  = a[6]*sc  + w*v1.z;  a[7]  = a[7]*sc  + w*v1.w;
        a[8]  = a[8]*sc  + w*v2.x;  a[9]  = a[9]*sc  + w*v2.y;
        a[10] = a[10]*sc + w*v2.z;  a[11] = a[11]*sc + w*v2.w;
        a[12] = a[12]*sc + w*v3.x;  a[13] = a[13]*sc + w*v3.y;
        a[14] = a[14]*sc + w*v3.z;  a[15] = a[15]*sc + w*v3.w;
        M = Mn;
    }
    float inv = 1.f / (D + 1e-9f);
    float4* op = (float4*)(agg + (size_t)n * HID + h * DH);
    op[0] = make_float4(a[0]*inv,  a[1]*inv,  a[2]*inv,  a[3]*inv);
    op[1] = make_float4(a[4]*inv,  a[5]*inv,  a[6]*inv,  a[7]*inv);
    op[2] = make_float4(a[8]*inv,  a[9]*inv,  a[10]*inv, a[11]*inv);
    op[3] = make_float4(a[12]*inv, a[13]*inv, a[14]*inv, a[15]*inv);
}

// ---------------- fragment-fed 3xTF32 mma GEMM --------------------------------------
// block = 128 rows x 64 cols, 8 warps = 4 row-groups (wy) x 2 col-groups (cg).
// warp tile = 32 rows x 32 cols = 2 m16-frags x 4 n8-frags.
// B delivered pre-packed: one LDS.128 per n-frag per k8 (bh0,bh1,bl0,bl1).
// QKV: blockIdx.y picks f0/f1/f2, colC = y*64 (ldC=192). else colB=colC=y*64.
// LN (gridDim.y==1, N==64): C = LN(resid + gemm(+bias)); cross-warp stats via smem.
// ACT: 0 none, 1 relu, 2 tanh.  M multiple of 128; K multiple of 32.
template <int ACT, bool HAS_BIAS, bool QKV, bool LN>
__global__ void __launch_bounds__(256)
gemmF(const float* __restrict__ A,
      const float4* __restrict__ f0, const float4* __restrict__ f1,
      const float4* __restrict__ f2,
      const float* __restrict__ bias, const float* __restrict__ resid,
      const float* __restrict__ gamma, const float* __restrict__ beta,
      float* __restrict__ C, int K, int ldA, int N, int ldC) {
    __shared__ float  As[KC][136];        // bank(frag load) = 8*gc+gr -> conflict-free
    __shared__ float4 BsF[4][8][32];      // [k8][ntg_local][lane]
    __shared__ float  redS[128][2];
    __shared__ float  redQ[128][2];

    const float4* fb;
    int colB, colC, ntgBase;
    if (QKV) {
        fb = (blockIdx.y == 0) ? f0 : ((blockIdx.y == 1) ? f1 : f2);
        colB = 0; colC = blockIdx.y * 64; ntgBase = 0;
    } else {
        fb = f0; colB = blockIdx.y * 64; colC = colB; ntgBase = blockIdx.y * 8;
    }
    int t = threadIdx.x;
    int rowBase = blockIdx.x * 128;
    int w = t >> 5, lane = t & 31;
    int gr = lane >> 2, gc = lane & 3;
    int wy = w >> 1, cg = w & 1;
    int rw = wy * 32;
    int nTG = N >> 3;

    float acc0[4][4], acc1[4][4];
#pragma unroll
    for (int i = 0; i < 4; i++)
#pragma unroll
        for (int j = 0; j < 4; j++) { acc0[i][j] = 0.f; acc1[i][j] = 0.f; }

    for (int kb = 0; kb < K; kb += KC) {
        // stage A: 128 rows x 32 k, transposed As[k][row]
#pragma unroll
        for (int i = 0; i < 4; i++) {
            int e4 = t + i * 256;
            int rr = e4 & 127;
            int k4 = e4 >> 7;
            float4 v = *(const float4*)(A + (size_t)(rowBase + rr) * ldA + kb + k4 * 4);
            As[k4 * 4 + 0][rr] = v.x; As[k4 * 4 + 1][rr] = v.y;
            As[k4 * 4 + 2][rr] = v.z; As[k4 * 4 + 3][rr] = v.w;
        }
        // stage B fragments: straight float4 copy
        int k8base = kb >> 3;
#pragma unroll
        for (int i = 0; i < 4; i++) {
            int e = t + i * 256;
            int bl = e & 31, nn = (e >> 5) & 7, k8l = e >> 8;
            BsF[k8l][nn][bl] =
                fb[((size_t)(k8base + k8l) * nTG + ntgBase + nn) * 32 + bl];
        }
        __syncthreads();

#pragma unroll
        for (int k8l = 0; k8l < 4; k8l++) {
            int k0 = k8l * 8;
            float a0 = As[k0 + gc]    [rw + gr];
            float a1 = As[k0 + gc]    [rw + gr + 8];
            float a2 = As[k0 + gc + 4][rw + gr];
            float a3 = As[k0 + gc + 4][rw + gr + 8];
            float a4 = As[k0 + gc]    [rw + 16 + gr];
            float a5 = As[k0 + gc]    [rw + 16 + gr + 8];
            float a6 = As[k0 + gc + 4][rw + 16 + gr];
            float a7 = As[k0 + gc + 4][rw + 16 + gr + 8];
            uint32_t ah0[4], al0[4], ah1[4], al1[4];
            ah0[0] = f2tf(a0); al0[0] = f2tf(a0 - __uint_as_float(ah0[0]));
            ah0[1] = f2tf(a1); al0[1] = f2tf(a1 - __uint_as_float(ah0[1]));
            ah0[2] = f2tf(a2); al0[2] = f2tf(a2 - __uint_as_float(ah0[2]));
            ah0[3] = f2tf(a3); al0[3] = f2tf(a3 - __uint_as_float(ah0[3]));
            ah1[0] = f2tf(a4); al1[0] = f2tf(a4 - __uint_as_float(ah1[0]));
            ah1[1] = f2tf(a5); al1[1] = f2tf(a5 - __uint_as_float(ah1[1]));
            ah1[2] = f2tf(a6); al1[2] = f2tf(a6 - __uint_as_float(ah1[2]));
            ah1[3] = f2tf(a7); al1[3] = f2tf(a7 - __uint_as_float(ah1[3]));
#pragma unroll
            for (int ntl = 0; ntl < 4; ntl++) {
                float4 bf = BsF[k8l][cg * 4 + ntl][lane];
                uint32_t bh0 = __float_as_uint(bf.x);
                uint32_t bh1 = __float_as_uint(bf.y);
                uint32_t bl0 = __float_as_uint(bf.z);
                uint32_t bl1 = __float_as_uint(bf.w);
                MMA_TF32(acc0[ntl], ah0, bh0, bh1);
                MMA_TF32(acc0[ntl], ah0, bl0, bl1);
                MMA_TF32(acc0[ntl], al0, bh0, bh1);
                MMA_TF32(acc1[ntl], ah1, bh0, bh1);
                MMA_TF32(acc1[ntl], ah1, bl0, bl1);
                MMA_TF32(acc1[ntl], al1, bh0, bh1);
            }
        }
        __syncthreads();
    }

    // epilogue. thread owns rows (rw+gr, +8, +16, +24), cols cg*32 + ntl*8 + 2gc (+1)
    if (HAS_BIAS) {
#pragma unroll
        for (int ntl = 0; ntl < 4; ntl++) {
            int c = colB + cg * 32 + ntl * 8 + 2 * gc;
            float b0 = __ldg(&bias[c]), b1 = __ldg(&bias[c + 1]);
            acc0[ntl][0] += b0; acc0[ntl][1] += b1;
            acc0[ntl][2] += b0; acc0[ntl][3] += b1;
            acc1[ntl][0] += b0; acc1[ntl][1] += b1;
            acc1[ntl][2] += b0; acc1[ntl][3] += b1;
        }
    }
    if (ACT == 1) {
#pragma unroll
        for (int ntl = 0; ntl < 4; ntl++)
#pragma unroll
            for (int j = 0; j < 4; j++) {
                acc0[ntl][j] = fmaxf(acc0[ntl][j], 0.f);
                acc1[ntl][j] = fmaxf(acc1[ntl][j], 0.f);
            }
    }
    if (ACT == 2) {
#pragma unroll
        for (int ntl = 0; ntl < 4; ntl++)
#pragma unroll
            for (int j = 0; j < 4; j++) {
                acc0[ntl][j] = tanhf(acc0[ntl][j]);
                acc1[ntl][j] = tanhf(acc1[ntl][j]);
            }
    }
    int lr0 = rw + gr;
    if (LN) {
        // add residual
#pragma unroll
        for (int ntl = 0; ntl < 4; ntl++) {
            int c = colC + cg * 32 + ntl * 8 + 2 * gc;
            float2 r0 = *(const float2*)(resid + (size_t)(rowBase + lr0)      * ldC + c);
            float2 r1 = *(const float2*)(resid + (size_t)(rowBase + lr0 + 8)  * ldC + c);
            float2 r2 = *(const float2*)(resid + (size_t)(rowBase + lr0 + 16) * ldC + c);
            float2 r3 = *(const float2*)(resid + (size_t)(rowBase + lr0 + 24) * ldC + c);
            acc0[ntl][0] += r0.x; acc0[ntl][1] += r0.y;
            acc0[ntl][2] += r1.x; acc0[ntl][3] += r1.y;
            acc1[ntl][0] += r2.x; acc1[ntl][1] += r2.y;
            acc1[ntl][2] += r3.x; acc1[ntl][3] += r3.y;
        }
        // per-row partial sum and sumsq (this warp's 32 cols)
        float s[4] = {0, 0, 0, 0}, q[4] = {0, 0, 0, 0};
#pragma unroll
        for (int ntl = 0; ntl < 4; ntl++) {
            s[0] += acc0[ntl][0] + acc0[ntl][1];
            q[0] += acc0[ntl][0]*acc0[ntl][0] + acc0[ntl][1]*acc0[ntl][1];
            s[1] += acc0[ntl][2] + acc0[ntl][3];
            q[1] += acc0[ntl][2]*acc0[ntl][2] + acc0[ntl][3]*acc0[ntl][3];
            s[2] += acc1[ntl][0] + acc1[ntl][1];
            q[2] += acc1[ntl][0]*acc1[ntl][0] + acc1[ntl][1]*acc1[ntl][1];
            s[3] += acc1[ntl][2] + acc1[ntl][3];
            q[3] += acc1[ntl][2]*acc1[ntl][2] + acc1[ntl][3]*acc1[ntl][3];
        }
#pragma unroll
        for (int o = 1; o < 4; o <<= 1)
#pragma unroll
            for (int j = 0; j < 4; j++) {
                s[j] += __shfl_xor_sync(0xffffffffu, s[j], o);
                q[j] += __shfl_xor_sync(0xffffffffu, q[j], o);
            }
#pragma unroll
        for (int j = 0; j < 4; j++) {
            redS[lr0 + 8 * j][cg] = s[j];
            redQ[lr0 + 8 * j][cg] = q[j];
        }
        __syncthreads();
        float mean[4], rs[4];
#pragma unroll
        for (int j = 0; j < 4; j++) {
            float tS = redS[lr0 + 8 * j][0] + redS[lr0 + 8 * j][1];
            float tQ = redQ[lr0 + 8 * j][0] + redQ[lr0 + 8 * j][1];
            mean[j] = tS * (1.f / HID);
            float var = tQ * (1.f / HID) - mean[j] * mean[j];
            rs[j] = rsqrtf(var + 1e-5f);
        }
#pragma unroll
        for (int ntl = 0; ntl < 4; ntl++) {
            int c = cg * 32 + ntl * 8 + 2 * gc;
            float g0 = __ldg(&gamma[c]), g1 = __ldg(&gamma[c + 1]);
            float b0 = __ldg(&beta[c]),  b1 = __ldg(&beta[c + 1]);
            acc0[ntl][0] = (acc0[ntl][0] - mean[0]) * rs[0] * g0 + b0;
            acc0[ntl][1] = (acc0[ntl][1] - mean[0]) * rs[0] * g1 + b1;
            acc0[ntl][2] = (acc0[ntl][2] - mean[1]) * rs[1] * g0 + b0;
            acc0[ntl][3] = (acc0[ntl][3] - mean[1]) * rs[1] * g1 + b1;
            acc1[ntl][0] = (acc1[ntl][0] - mean[2]) * rs[2] * g0 + b0;
            acc1[ntl][1] = (acc1[ntl][1] - mean[2]) * rs[2] * g1 + b1;
            acc1[ntl][2] = (acc1[ntl][2] - mean[3]) * rs[3] * g0 + b0;
            acc1[ntl][3] = (acc1[ntl][3] - mean[3]) * rs[3] * g1 + b1;
        }
    }
#pragma unroll
    for (int ntl = 0; ntl < 4; ntl++) {
        int c = colC + cg * 32 + ntl * 8 + 2 * gc;
        *(float2*)(C + (size_t)(rowBase + lr0)      * ldC + c) = make_float2(acc0[ntl][0], acc0[ntl][1]);
        *(float2*)(C + (size_t)(rowBase + lr0 + 8)  * ldC + c) = make_float2(acc0[ntl][2], acc0[ntl][3]);
        *(float2*)(C + (size_t)(rowBase + lr0 + 16) * ldC + c) = make_float2(acc1[ntl][0], acc1[ntl][1]);
        *(float2*)(C + (size_t)(rowBase + lr0 + 24) * ldC + c) = make_float2(acc1[ntl][2], acc1[ntl][3]);
    }
}

// ---------------- readout: gat_out -> feat[:,0:15], obs -> feat[:,15:1515], pad 0 -----
__global__ void readout_kernel(const float* __restrict__ x, const int* __restrict__ agents,
                               const float* __restrict__ Wr, const float* __restrict__ br,
                               const float* __restrict__ obs, float* __restrict__ feat) {
    int row = blockIdx.x;
    __shared__ float sx[HID];
    int node = agents[row];
    if (threadIdx.x < HID) sx[threadIdx.x] = x[(size_t)node * HID + threadIdx.x];
    __syncthreads();
    if (threadIdx.x < AOUT) {
        float acc = br[threadIdx.x];
        for (int k = 0; k < HID; k++) acc += sx[k] * Wr[k * AOUT + threadIdx.x];
        feat[(size_t)row * FPAD + threadIdx.x] = acc;
    }
    for (int i = threadIdx.x; i < OBSD; i += blockDim.x)
        feat[(size_t)row * FPAD + AOUT + i] = obs[(size_t)row * OBSD + i];
    if (threadIdx.x < FPAD - FEATD)
        feat[(size_t)row * FPAD + FEATD + threadIdx.x] = 0.f;
}

// ---------------- obs zero-padded copy ----------------
__global__ void obspad_kernel(const float* __restrict__ obs, float* __restrict__ dst) {
    int row = blockIdx.x;
    for (int i = threadIdx.x; i < FPAD; i += blockDim.x)
        dst[(size_t)row * FPAD + i] = (i < OBSD) ? obs[(size_t)row * OBSD + i] : 0.f;
}

// ---------------- small FC (only tiny-N heads: Wlog N=15, Wvo N=1) --------------------
__global__ void fc_kernel(const float* __restrict__ in, int ldIn,
                          const float* __restrict__ W, const float* __restrict__ bias,
                          float* __restrict__ out, int ldOut,
                          int K, int N, int act) {
    extern __shared__ float s_in[];
    int row = blockIdx.x;
    for (int i = threadIdx.x; i < K; i += blockDim.x)
        s_in[i] = in[(size_t)row * ldIn + i];
    __syncthreads();
    int n = threadIdx.x;
    if (n >= N) return;
    float acc = bias ? __ldg(&bias[n]) : 0.f;
    int k = 0;
    for (; k + 4 <= K; k += 4) {
        acc += s_in[k]     * W[(size_t)k       * N + n];
        acc += s_in[k + 1] * W[(size_t)(k + 1) * N + n];
        acc += s_in[k + 2] * W[(size_t)(k + 2) * N + n];
        acc += s_in[k + 3] * W[(size_t)(k + 3) * N + n];
    }
    for (; k < K; k++) acc += s_in[k] * W[(size_t)k * N + n];
    if (act) acc = tanhf(acc);
    out[(size_t)row * ldOut + n] = acc;
}

// ---------------- launch ----------------
extern "C" void kernel_launch(void* const* d_in, const int* in_sizes, int n_in,
                              void* d_out, int out_size) {
    const float* node_feats = (const float*)d_in[0];
    const float* obs        = (const float*)d_in[1];
    const int*   edge_src   = (const int*)d_in[2];
    const int*   edge_dst   = (const int*)d_in[3];
    const int*   agents     = (const int*)d_in[4];
    const float* W_in = (const float*)d_in[5];
    const float* Wq   = (const float*)d_in[6];
    const float* Wk   = (const float*)d_in[7];
    const float* Wv   = (const float*)d_in[8];
    const float* Wo   = (const float*)d_in[9];
    const float* ln1g = (const float*)d_in[10];
    const float* ln1b = (const float*)d_in[11];
    const float* W1   = (const float*)d_in[12];
    const float* b1   = (const float*)d_in[13];
    const float* W2   = (const float*)d_in[14];
    const float* b2   = (const float*)d_in[15];
    const float* ln2g = (const float*)d_in[16];
    const float* ln2b = (const float*)d_in[17];
    const float* Wr   = (const float*)d_in[18];
    const float* br   = (const float*)d_in[19];
    const float* Wp1  = (const float*)d_in[20];
    const float* bp1  = (const float*)d_in[21];
    const float* Wp2  = (const float*)d_in[22];
    const float* bp2  = (const float*)d_in[23];
    const float* Wlog = (const float*)d_in[24];
    const float* blog = (const float*)d_in[25];
    const float* Wv1  = (const float*)d_in[26];
    const float* bv1  = (const float*)d_in[27];
    const float* Wv2  = (const float*)d_in[28];
    const float* bv2  = (const float*)d_in[29];
    const float* Wvo  = (const float*)d_in[30];
    const float* bvo  = (const float*)d_in[31];
    float* out = (float*)d_out;

    float *x_p, *qkv_p, *agg_p, *h_p, *feat_p, *obsP_p, *f1_p, *f2_p, *vh_p, *vh2_p;
    float4* fr;
    int* cnt_p;
    cudaGetSymbolAddress((void**)&x_p,   g_x);
    cudaGetSymbolAddress((void**)&qkv_p, g_qkv);
    cudaGetSymbolAddress((void**)&agg_p, g_agg);
    cudaGetSymbolAddress((void**)&h_p,   g_h);
    cudaGetSymbolAddress((void**)&feat_p, g_feat);
    cudaGetSymbolAddress((void**)&obsP_p, g_obsP);
    cudaGetSymbolAddress((void**)&f1_p,  g_f1);
    cudaGetSymbolAddress((void**)&f2_p,  g_f2);
    cudaGetSymbolAddress((void**)&vh_p,  g_vh);
    cudaGetSymbolAddress((void**)&vh2_p, g_vh2);
    cudaGetSymbolAddress((void**)&fr,    g_frag);
    cudaGetSymbolAddress((void**)&cnt_p, g_cnt);

    const int GX = TOT_N / 128;          // 1000 row-blocks

    // CSR build
    cudaMemsetAsync(cnt_p, 0, TOT_N * sizeof(int));
    count_kernel<<<(NEDGE + 255) / 256, 256>>>(edge_dst);
    scan_kernel<<<1, 1024>>>();
    cudaMemsetAsync(cnt_p, 0, TOT_N * sizeof(int));
    scatter_kernel<<<(NEDGE + 255) / 256, 256>>>(edge_src, edge_dst);

    // weight fragment repacks
    #define RPK(src, off, Ks, Kp, N, L) \
        repack_kernel<<<((L) * ((Kp)/8) * ((N)/8) * 32 + 255) / 256, 256>>>( \
            src, fr + (off), Ks, Kp, N, L)
    RPK(W_in, FR_WIN, FIN, FIN, HID, 1);
    RPK(Wq,   FR_WQ,  HID, HID, HID, NLAYERS);
    RPK(Wk,   FR_WK,  HID, HID, HID, NLAYERS);
    RPK(Wv,   FR_WV,  HID, HID, HID, NLAYERS);
    RPK(Wo,   FR_WO,  HID, HID, HID, NLAYERS);
    RPK(W1,   FR_W1,  HID, HID, 2 * HID, NLAYERS);
    RPK(W2,   FR_W2,  2 * HID, 2 * HID, HID, NLAYERS);
    RPK(Wp1,  FR_WP1, FEATD, FPAD, HSZ, 1);
    RPK(Wp2,  FR_WP2, HSZ, HSZ, HSZ, 1);
    RPK(Wv1,  FR_WV1, OBSD, FPAD, VH, 1);
    RPK(Wv2,  FR_WV2, VH, VH, VH, 1);

    // input projection: x = node_feats @ W_in   (K=32)
    gemmF<0, false, false, false><<<dim3(GX, 1), 256>>>(
        node_feats, fr + FR_WIN, nullptr, nullptr,
        nullptr, nullptr, nullptr, nullptr, x_p, FIN, FIN, HID, HID);

    for (int l = 0; l < NLAYERS; l++) {
        // fused qkv: [n,192] = x @ [Wq|Wk|Wv]
        gemmF<0, false, true, false><<<dim3(GX, 3), 256>>>(
            x_p, fr + FR_WQ + l * 2048, fr + FR_WK + l * 2048, fr + FR_WV + l * 2048,
            nullptr, nullptr, nullptr, nullptr, qkv_p, HID, HID, HID, 3 * HID);

        attn_kernel<<<(TOT_N * NHEADS + 255) / 256, 256>>>(qkv_p, agg_p);

        // x = LN(x + agg @ Wo)
        gemmF<0, false, false, true><<<dim3(GX, 1), 256>>>(
            agg_p, fr + FR_WO + l * 2048, nullptr, nullptr,
            nullptr, x_p, ln1g + l * HID, ln1b + l * HID, x_p, HID, HID, HID, HID);

        // h = relu(x @ W1 + b1)
        gemmF<1, true, false, false><<<dim3(GX, 2), 256>>>(
            x_p, fr + FR_W1 + l * 4096, nullptr, nullptr,
            b1 + (size_t)l * 2 * HID, nullptr, nullptr, nullptr,
            h_p, HID, HID, 2 * HID, 2 * HID);

        // x = LN(x + h @ W2 + b2)
        gemmF<0, true, false, true><<<dim3(GX, 1), 256>>>(
            h_p, fr + FR_W2 + l * 4096, nullptr, nullptr,
            b2 + (size_t)l * HID, x_p, ln2g + l * HID, ln2b + l * HID,
            x_p, 2 * HID, 2 * HID, HID, HID);
    }

    // readout + concat with obs (padded to 1536)
    readout_kernel<<<NB, 256>>>(x_p, agents, Wr, br, obs, feat_p);
    obspad_kernel<<<NB, 256>>>(obs, obsP_p);

    // policy head: f1 = tanh(feat @ Wp1 + bp1); f2 = tanh(f1 @ Wp2 + bp2)
    gemmF<2, true, false, false><<<dim3(1, HSZ / 64), 256>>>(
        feat_p, fr + FR_WP1, nullptr, nullptr,
        bp1, nullptr, nullptr, nullptr, f1_p, FPAD, FPAD, HSZ, HSZ);
    gemmF<2, true, false, false><<<dim3(1, HSZ / 64), 256>>>(
        f1_p, fr + FR_WP2, nullptr, nullptr,
        bp2, nullptr, nullptr, nullptr, f2_p, HSZ, HSZ, HSZ, HSZ);
    fc_kernel<<<NB, HSZ, HSZ * sizeof(float)>>>(f2_p, HSZ, Wlog, blog, out, AOUT, HSZ, AOUT, 0);

    // value head
    gemmF<2, true, false, false><<<dim3(1, VH / 64), 256>>>(
        obsP_p, fr + FR_WV1, nullptr, nullptr,
        bv1, nullptr, nullptr, nullptr, vh_p, FPAD, FPAD, VH, VH);
    gemmF<2, true, false, false><<<dim3(1, VH / 64), 256>>>(
        vh_p, fr + FR_WV2, nullptr, nullptr,
        bv2, nullptr, nullptr, nullptr, vh2_p, VH, VH, VH, VH);
    fc_kernel<<<NB, 128, VH * sizeof(float)>>>(vh2_p, VH, Wvo, bvo, out + NB * AOUT, 1, VH, 1, 0);
}